// round 7
// baseline (speedup 1.0000x reference)
#include <cuda_runtime.h>
#include <cuda_fp16.h>
#include <math.h>
#include <stdint.h>

// ---------------- problem constants ----------------
#define T_TOK 8192
#define HID   1024
#define NEXP  64
#define KTOP  2
#define CAP   1024
#define FFN   512
#define SFFN  1024
#define NASSIGN (T_TOK*KTOP)

// ---------------- helpers (compute_103-safe PTX only) ----------------
__device__ __forceinline__ uint32_t smem_u32(const void* p) {
    uint32_t a;
    asm("{ .reg .u64 t; cvta.to.shared.u64 t, %1; cvt.u32.u64 %0, t; }" : "=r"(a) : "l"(p));
    return a;
}
__device__ __forceinline__ void ldm_x4(uint32_t addr, uint32_t& r0, uint32_t& r1,
                                       uint32_t& r2, uint32_t& r3) {
    asm volatile("ldmatrix.sync.aligned.m8n8.x4.shared.b16 {%0,%1,%2,%3}, [%4];"
        : "=r"(r0), "=r"(r1), "=r"(r2), "=r"(r3) : "r"(addr));
}
__device__ __forceinline__ void ldm_x4t(uint32_t addr, uint32_t& r0, uint32_t& r1,
                                        uint32_t& r2, uint32_t& r3) {
    asm volatile("ldmatrix.sync.aligned.m8n8.x4.trans.shared.b16 {%0,%1,%2,%3}, [%4];"
        : "=r"(r0), "=r"(r1), "=r"(r2), "=r"(r3) : "r"(addr));
}
__device__ __forceinline__ void mma_fp16(float* d, const uint32_t* a, uint32_t b0, uint32_t b1) {
    asm volatile("mma.sync.aligned.m16n8k16.row.col.f32.f16.f16.f32 "
        "{%0,%1,%2,%3}, {%4,%5,%6,%7}, {%8,%9}, {%0,%1,%2,%3};"
        : "+f"(d[0]), "+f"(d[1]), "+f"(d[2]), "+f"(d[3])
        : "r"(a[0]), "r"(a[1]), "r"(a[2]), "r"(a[3]), "r"(b0), "r"(b1));
}
__device__ __forceinline__ void cp16(uint32_t dst, const void* src) {
    size_t g = __cvta_generic_to_global(src);
    asm volatile("cp.async.cg.shared.global [%0], [%1], 16;" :: "r"(dst), "l"(g));
}
#define CP_COMMIT() asm volatile("cp.async.commit_group;" ::: "memory")
#define CP_WAIT1()  asm volatile("cp.async.wait_group 1;" ::: "memory")
// A tiles: 128B rows -> chunk[4:6] ^= row&7
#define SWA(o) ((o) ^ (((o) >> 3) & 0x70))
// B tiles: 512B rows -> chunk[4:6] ^= k&7
#define SWB(o) ((o) ^ (((o) >> 5) & 0x70))

// ---------------- scratch (device globals; allocation is forbidden) ----------
__device__ float g_logits[T_TOK * NEXP];
__device__ int   g_topi[NASSIGN];
__device__ float g_topv[NASSIGN];
__device__ int   g_counts[NEXP];
__device__ int   g_listcnt[NEXP];
__device__ float g_psum[NEXP];
__device__ int   g_assign[NEXP * CAP];

__device__ __align__(16) __half g_xh[T_TOK * HID];                  // 16 MB
__device__ __align__(16) __half g_w1h[(size_t)NEXP * HID * FFN];    // 64 MB
__device__ __align__(16) __half g_w2h[(size_t)NEXP * FFN * HID];    // 64 MB
__device__ __align__(16) __half g_ws1h[(size_t)HID * SFFN];
__device__ __align__(16) __half g_ws2h[(size_t)SFFN * HID];
__device__ __align__(16) __half g_h[(size_t)NEXP * CAP * FFN];      // 64 MB
__device__ __align__(16) __half g_s[(size_t)T_TOK * SFFN];          // 16 MB

__device__ __forceinline__ float gelu_f(float x) {
    float x3 = x * x * x;
    return 0.5f * x * (1.0f + tanhf(0.7978845608028654f * (x + 0.044715f * x3)));
}

// ---------------- prepass: fp32 -> fp16, MLP-4 streaming ----------------
__device__ __forceinline__ uint2 pack4(float4 v) {
    uint2 r;
    __half2 a = __floats2half2_rn(v.x, v.y);
    __half2 b = __floats2half2_rn(v.z, v.w);
    r.x = *reinterpret_cast<uint32_t*>(&a);
    r.y = *reinterpret_cast<uint32_t*>(&b);
    return r;
}
__global__ void cvt1(const float4* __restrict__ in, uint2* __restrict__ o, int n4) {
    int g = gridDim.x * blockDim.x;
    int i = blockIdx.x * blockDim.x + threadIdx.x;
    for (; i + 3 * g < n4; i += 4 * g) {
        float4 v0 = in[i], v1 = in[i + g], v2 = in[i + 2 * g], v3 = in[i + 3 * g];
        o[i]         = pack4(v0);
        o[i + g]     = pack4(v1);
        o[i + 2 * g] = pack4(v2);
        o[i + 3 * g] = pack4(v3);
    }
    for (; i < n4; i += g) o[i] = pack4(in[i]);
}

// ---------------- zero bookkeeping ----------------
__global__ void zero_kernel() {
    int i = threadIdx.x;
    if (i < NEXP) { g_counts[i] = 0; g_listcnt[i] = 0; g_psum[i] = 0.0f; }
}

// ---------------- exact fp32 router GEMM ----------------
#define RTM 64
#define RTK 16
__global__ void router_sgemm(const float* __restrict__ A, const float* __restrict__ B,
                             float* __restrict__ Cc)
{
    __shared__ float As[RTK][RTM + 4];
    __shared__ float Bs[RTK][64];
    int tid = threadIdx.x;
    int tx = tid & 15, ty = tid >> 4;
    int bm = blockIdx.y * RTM;
    int la_m = tid >> 2, la_k = (tid & 3) * 4;
    int lb_k = tid >> 4, lb_n = (tid & 15) * 4;
    float acc[4][4];
#pragma unroll
    for (int i = 0; i < 4; i++)
#pragma unroll
        for (int j = 0; j < 4; j++) acc[i][j] = 0.0f;
    for (int k0 = 0; k0 < HID; k0 += RTK) {
        float4 av = *reinterpret_cast<const float4*>(A + (size_t)(bm + la_m) * HID + k0 + la_k);
        As[la_k + 0][la_m] = av.x; As[la_k + 1][la_m] = av.y;
        As[la_k + 2][la_m] = av.z; As[la_k + 3][la_m] = av.w;
        float4 bv = *reinterpret_cast<const float4*>(B + (size_t)(k0 + lb_k) * NEXP + lb_n);
        Bs[lb_k][lb_n + 0] = bv.x; Bs[lb_k][lb_n + 1] = bv.y;
        Bs[lb_k][lb_n + 2] = bv.z; Bs[lb_k][lb_n + 3] = bv.w;
        __syncthreads();
#pragma unroll
        for (int kk = 0; kk < RTK; kk++) {
            float a[4], b[4];
#pragma unroll
            for (int i = 0; i < 4; i++) a[i] = As[kk][ty * 4 + i];
#pragma unroll
            for (int j = 0; j < 4; j++) b[j] = Bs[kk][tx * 4 + j];
#pragma unroll
            for (int i = 0; i < 4; i++)
#pragma unroll
                for (int j = 0; j < 4; j++) acc[i][j] += a[i] * b[j];
        }
        __syncthreads();
    }
#pragma unroll
    for (int i = 0; i < 4; i++)
#pragma unroll
        for (int j = 0; j < 4; j++)
            Cc[(size_t)(bm + ty * 4 + i) * NEXP + tx * 4 + j] = acc[i][j];
}

// ---------------- router top-k / softmax / counts ----------------
__global__ void topk_kernel() {
    int warp = threadIdx.x >> 5, lane = threadIdx.x & 31;
    int t = blockIdx.x * 4 + warp;
    if (t >= T_TOK) return;
    float s0 = g_logits[t * NEXP + lane];
    float s1 = g_logits[t * NEXP + 32 + lane];
    float m = fmaxf(s0, s1);
#pragma unroll
    for (int o = 16; o; o >>= 1) m = fmaxf(m, __shfl_xor_sync(0xffffffffu, m, o));
    float e0 = expf(s0 - m), e1 = expf(s1 - m);
    float d = e0 + e1;
#pragma unroll
    for (int o = 16; o; o >>= 1) d += __shfl_xor_sync(0xffffffffu, d, o);
    float p0 = e0 / d, p1 = e1 / d;

    float mx = fmaxf(p0, p1);
#pragma unroll
    for (int o = 16; o; o >>= 1) mx = fmaxf(mx, __shfl_xor_sync(0xffffffffu, mx, o));
    int cand = 0x7fffffff;
    if (p0 == mx) cand = lane;
    if (p1 == mx) cand = min(cand, lane + 32);
#pragma unroll
    for (int o = 16; o; o >>= 1) cand = min(cand, __shfl_xor_sync(0xffffffffu, cand, o));
    int i1 = cand; float v1 = mx;

    float q0 = (lane == i1) ? -1e30f : p0;
    float q1 = (lane + 32 == i1) ? -1e30f : p1;
    float mx2 = fmaxf(q0, q1);
#pragma unroll
    for (int o = 16; o; o >>= 1) mx2 = fmaxf(mx2, __shfl_xor_sync(0xffffffffu, mx2, o));
    int cand2 = 0x7fffffff;
    if (q0 == mx2) cand2 = lane;
    if (q1 == mx2) cand2 = min(cand2, lane + 32);
#pragma unroll
    for (int o = 16; o; o >>= 1) cand2 = min(cand2, __shfl_xor_sync(0xffffffffu, cand2, o));
    int i2 = cand2; float v2 = mx2;

    if (lane == 0) {
        g_topi[t * 2 + 0] = i1; g_topv[t * 2 + 0] = v1;
        g_topi[t * 2 + 1] = i2; g_topv[t * 2 + 1] = v2;
        atomicAdd(&g_counts[i1], 1);
        atomicAdd(&g_counts[i2], 1);
    }
    atomicAdd(&g_psum[lane], p0);
    atomicAdd(&g_psum[lane + 32], p1);
}

// ---------------- build per-expert slot lists ----------------
__global__ void build_kernel() {
    int a = blockIdx.x * blockDim.x + threadIdx.x;
    if (a >= NASSIGN) return;
    int e = g_topi[a];
    int pos = atomicAdd(&g_listcnt[e], 1);
    if (pos < CAP) g_assign[e * CAP + pos] = a;
}

// ---------------- fp16 mma.sync GEMM, CTA 128x256, warp tile 64x64 ----------------
// C[M,N] = A[M,K] @ B[K,N]   (B row-major [K][N], loaded via ldmatrix.trans)
// K-chunk 64, 3-stage cp.async pipeline, 8 warps (2x4), 1 CTA/SM.
// EPI: 0 = gelu -> fp16 out, 1 = f32 store, 2 = atomic combine into out[token]
#define STAGE_BYTES 49152    // A 16K + B 32K
#define MISC_OFF    147456   // 3 stages
#define TROW        264      // padded f32 tile row (256 + 8)

template<int EPI, bool GATHER, bool EXPERT>
__global__ void __launch_bounds__(256, 1)
mma_gemm(const __half* __restrict__ A, int lda, long aBatch,
         const __half* __restrict__ B, int ldb, long bBatch,
         __half* __restrict__ outH, float* __restrict__ outF, int ldc, long cBatch,
         int M, int Kd)
{
    extern __shared__ char smem[];
    const int tid = threadIdx.x;
    const int lane = tid & 31, warp = tid >> 5;
    const int wm = warp & 1, wn = warp >> 1;      // 2 x 4 warp grid
    const int bm = blockIdx.y * 128, bn = blockIdx.x * 256;

    int e = 0, cnt = M;
    if (EXPERT) {
        e = blockIdx.z;
        cnt = min(g_listcnt[e], CAP);
        if (bm >= cnt) return;
        if (aBatch) A += (size_t)e * aBatch;
        B += (size_t)e * bBatch;
        if (EPI == 0) outH += (size_t)e * cBatch;
    }

    int*   tok = (int*)(smem + MISC_OFF);
    float* pw  = (float*)(smem + MISC_OFF + 512);
    if ((GATHER || EPI == 2) && tid < 128) {
        int idx = min(bm + tid, cnt - 1);
        int a = g_assign[e * CAP + idx];
        tok[tid] = a >> 1;                    // token (KTOP=2)
        pw[tid]  = g_topv[a];
    }
    __syncthreads();

    uint32_t sb = smem_u32(smem);
    const int NC = Kd >> 6;

#define ISSUE_CHUNK(cc, ss) do {                                              \
    int k0_ = (cc) * 64;                                                      \
    uint32_t st_ = sb + (ss) * STAGE_BYTES;                                   \
    for (int p = tid; p < 1024; p += 256) {       /* A: 128 x 64 fp16 */      \
        int r_ = p >> 3, q_ = p & 7;                                          \
        size_t row_ = GATHER ? (size_t)tok[r_] : (size_t)(bm + r_);           \
        cp16(st_ + SWA((uint32_t)(r_ * 128 + q_ * 16)),                       \
             A + row_ * lda + k0_ + q_ * 8);                                  \
    }                                                                         \
    for (int p = tid; p < 2048; p += 256) {       /* B: 64 x 256 fp16 */      \
        int kr_ = p >> 5, nq_ = p & 31;                                       \
        cp16(st_ + 16384 + SWB((uint32_t)(kr_ * 512 + nq_ * 16)),             \
             B + (size_t)(k0_ + kr_) * ldb + bn + nq_ * 8);                   \
    } } while (0)

    ISSUE_CHUNK(0, 0); CP_COMMIT();
    ISSUE_CHUNK(1, 1); CP_COMMIT();

    float acc[4][8][4];
#pragma unroll
    for (int a = 0; a < 4; a++)
#pragma unroll
        for (int b = 0; b < 8; b++)
#pragma unroll
            for (int c = 0; c < 4; c++) acc[a][b][c] = 0.0f;

    for (int c = 0; c < NC; ++c) {
        CP_WAIT1();
        __syncthreads();
        if (c + 2 < NC) { ISSUE_CHUNK(c + 2, (c + 2) % 3); }
        CP_COMMIT();
        uint32_t sA = sb + (c % 3) * STAGE_BYTES;
        uint32_t sB = sA + 16384;
#pragma unroll
        for (int kk = 0; kk < 4; kk++) {
            uint32_t af[4][4];
#pragma unroll
            for (int mt = 0; mt < 4; mt++) {
                uint32_t off = SWA((uint32_t)((wm * 64 + mt * 16 + (lane & 15)) * 128
                                              + kk * 32 + ((lane >> 4) << 4)));
                ldm_x4(sA + off, af[mt][0], af[mt][1], af[mt][2], af[mt][3]);
            }
#pragma unroll
            for (int ntp = 0; ntp < 4; ntp++) {
                uint32_t boff = SWB((uint32_t)((kk * 16 + (lane & 15)) * 512
                                + (wn * 64 + ntp * 16 + ((lane >> 4) << 3)) * 2));
                uint32_t b0, b1, b2, b3;
                ldm_x4t(sB + boff, b0, b1, b2, b3);
#pragma unroll
                for (int mt = 0; mt < 4; mt++) {
                    mma_fp16(acc[mt][ntp * 2],     af[mt], b0, b1);
                    mma_fp16(acc[mt][ntp * 2 + 1], af[mt], b2, b3);
                }
            }
        }
    }
#undef ISSUE_CHUNK

    const int gr = lane >> 2, gc = (lane & 3) * 2;
    if (EPI == 2) {
        __syncthreads();   // stages dead; reuse as f32 tile
        float* tile = (float*)smem;   // 128 x TROW
#pragma unroll
        for (int mt = 0; mt < 4; mt++)
#pragma unroll
            for (int nt = 0; nt < 8; nt++)
#pragma unroll
                for (int h = 0; h < 2; h++) {
                    int rl = wm * 64 + mt * 16 + gr + h * 8;
                    int cl = wn * 64 + nt * 8 + gc;
                    *reinterpret_cast<float2*>(&tile[rl * TROW + cl]) =
                        make_float2(acc[mt][nt][2 * h], acc[mt][nt][2 * h + 1]);
                }
        __syncthreads();
        for (int r = warp; r < 128; r += 8) {
            if (bm + r < cnt) {
                float p = pw[r];
                float* base = outF + (size_t)tok[r] * HID + bn;
                for (int cc = lane; cc < 256; cc += 32)
                    atomicAdd(base + cc, p * tile[r * TROW + cc]);
            }
        }
    } else {
#pragma unroll
        for (int mt = 0; mt < 4; mt++)
#pragma unroll
            for (int nt = 0; nt < 8; nt++)
#pragma unroll
                for (int h = 0; h < 2; h++) {
                    int r = bm + wm * 64 + mt * 16 + gr + h * 8;
                    if (r >= cnt) continue;
                    int col = bn + wn * 64 + nt * 8 + gc;
                    if (EPI == 0) {
                        __half2 hv = __floats2half2_rn(gelu_f(acc[mt][nt][2 * h]),
                                                       gelu_f(acc[mt][nt][2 * h + 1]));
                        *reinterpret_cast<__half2*>(outH + (size_t)r * ldc + col) = hv;
                    } else {
                        *reinterpret_cast<float2*>(outF + (size_t)r * ldc + col) =
                            make_float2(acc[mt][nt][2 * h], acc[mt][nt][2 * h + 1]);
                    }
                }
    }
}

// ---------------- aux loss ----------------
__global__ void aux_kernel(float* __restrict__ out, int out_size)
{
    __shared__ float vals[NEXP];
    int i = threadIdx.x;
    if (i < NEXP) {
        float f = (float)g_counts[i] / (float)(T_TOK * KTOP);
        float P = g_psum[i] / (float)T_TOK;
        vals[i] = f * P;
    }
    __syncthreads();
    if (i == 0) {
        float s = 0.0f;
        for (int j = 0; j < NEXP; j++) s += vals[j];
        if (out_size > T_TOK * HID) out[T_TOK * HID] = 0.01f * (float)NEXP * s;
    }
}

// ---------------- launch ----------------
extern "C" void kernel_launch(void* const* d_in, const int* in_sizes, int n_in,
                              void* d_out, int out_size)
{
    const float* x        = (const float*)d_in[0];  // [T,H]
    const float* w_router = (const float*)d_in[1];  // [H,E]
    const float* w1       = (const float*)d_in[2];  // [E,H,F]
    const float* w2       = (const float*)d_in[3];  // [E,F,H]
    const float* ws1      = (const float*)d_in[4];  // [H,SF]
    const float* ws2      = (const float*)d_in[5];  // [SF,H]
    float* out = (float*)d_out;

    float* logits; cudaGetSymbolAddress((void**)&logits, g_logits);
    __half *xh, *w1h, *w2h, *ws1h, *ws2h, *hbuf, *sbuf;
    cudaGetSymbolAddress((void**)&xh,  g_xh);
    cudaGetSymbolAddress((void**)&w1h, g_w1h);
    cudaGetSymbolAddress((void**)&w2h, g_w2h);
    cudaGetSymbolAddress((void**)&ws1h, g_ws1h);
    cudaGetSymbolAddress((void**)&ws2h, g_ws2h);
    cudaGetSymbolAddress((void**)&hbuf, g_h);
    cudaGetSymbolAddress((void**)&sbuf, g_s);

    const int SMB = MISC_OFF + 1024;   // 3 stages + tok/pw
    cudaFuncSetAttribute(mma_gemm<0, true,  true >, cudaFuncAttributeMaxDynamicSharedMemorySize, SMB);
    cudaFuncSetAttribute(mma_gemm<2, false, true >, cudaFuncAttributeMaxDynamicSharedMemorySize, SMB);
    cudaFuncSetAttribute(mma_gemm<0, false, false>, cudaFuncAttributeMaxDynamicSharedMemorySize, SMB);
    cudaFuncSetAttribute(mma_gemm<1, false, false>, cudaFuncAttributeMaxDynamicSharedMemorySize, SMB);

    // ---- prepass conversions (MLP-4 streaming) ----
    cvt1<<<1024, 256>>>((const float4*)x,   (uint2*)xh,   T_TOK * HID / 4);
    cvt1<<<1024, 256>>>((const float4*)w1,  (uint2*)w1h,  NEXP * HID * FFN / 4);
    cvt1<<<1024, 256>>>((const float4*)w2,  (uint2*)w2h,  NEXP * FFN * HID / 4);
    cvt1<<<1024, 256>>>((const float4*)ws1, (uint2*)ws1h, HID * SFFN / 4);
    cvt1<<<1024, 256>>>((const float4*)ws2, (uint2*)ws2h, SFFN * HID / 4);

    zero_kernel<<<1, 256>>>();

    // ---- router (exact fp32) + routing ----
    router_sgemm<<<dim3(1, T_TOK / RTM), 256>>>(x, w_router, logits);
    topk_kernel<<<T_TOK / 4, 128>>>();
    build_kernel<<<(NASSIGN + 255) / 256, 256>>>();

    // ---- shared expert (writes base of out) ----
    mma_gemm<0, false, false><<<dim3(SFFN / 256, T_TOK / 128), 256, SMB>>>(
        xh, HID, 0, ws1h, SFFN, 0, sbuf, nullptr, SFFN, 0, T_TOK, HID);
    mma_gemm<1, false, false><<<dim3(HID / 256, T_TOK / 128), 256, SMB>>>(
        sbuf, SFFN, 0, ws2h, HID, 0, nullptr, out, HID, 0, T_TOK, SFFN);

    // ---- expert MLP; gemm2 atomically combines into out ----
    mma_gemm<0, true, true><<<dim3(FFN / 256, CAP / 128, NEXP), 256, SMB>>>(
        xh, HID, 0, w1h, FFN, (long)HID * FFN, hbuf, nullptr, FFN, (long)CAP * FFN,
        CAP, HID);
    mma_gemm<2, false, true><<<dim3(HID / 256, CAP / 128, NEXP), 256, SMB>>>(
        hbuf, FFN, (long)CAP * FFN, w2h, HID, (long)FFN * HID,
        nullptr, out, HID, 0, CAP, FFN);

    aux_kernel<<<1, 64>>>(out, out_size);
}